// round 1
// baseline (speedup 1.0000x reference)
#include <cuda_runtime.h>
#include <math.h>

// ---------------- problem constants ----------------
#define IMG     256
#define VIEWS   128
#define NDET    512
#define NS      364          // ceil(2R/STEP)+1, R = 256*sqrt(2)/2
#define SIDf    750.0f
#define SDDf    1250.0f
#define DET_ELT 1.2f
#define Rf      181.01933598375618f   // 256*sqrt(2)/2
// image coords: jx = px + 127.5 ; iy = 127.5 - py   (PIX = 1, STEP = 1)

// ---------------- packed padded image ----------------
// cell (i,j) holds {x0(i,j), x1(i,j), x0(i,j+1), x1(i,j+1)}
// padded by PAD cells of zeros on every side so all clipped-range gathers
// are branch-free and out-of-image corners contribute exactly 0.
#define PAD 4
#define PW  272              // 256 + 2*PAD + slack, float4 stride
#define PH  272

__device__ float4 g_pack[PH * PW];

__global__ void pack_kernel(const float* __restrict__ x) {
    int idx = blockIdx.x * blockDim.x + threadIdx.x;
    if (idx >= PH * PW) return;
    int row = idx / PW, col = idx % PW;
    int i = row - PAD, j = col - PAD;
    float a = 0.f, b = 0.f, c = 0.f, d = 0.f;
    if (i >= 0 && i < IMG) {
        if (j >= 0 && j < IMG) {
            a = x[i * IMG + j];
            b = x[IMG * IMG + i * IMG + j];
        }
        int j1 = j + 1;
        if (j1 >= 0 && j1 < IMG) {
            c = x[i * IMG + j1];
            d = x[IMG * IMG + i * IMG + j1];
        }
    }
    g_pack[idx] = make_float4(a, b, c, d);
}

// ---------------- main projection kernel ----------------
// one thread per (view, detector) ray; accumulates both batch images.
__global__ void __launch_bounds__(128) fpj_kernel(float* __restrict__ out) {
    const int n = blockIdx.x * blockDim.x + threadIdx.x;   // detector index
    const int v = blockIdx.y;                               // view index

    // ---- geometry (matches reference float32 math) ----
    // beta = deg2rad(360*v/128); 2.8125*v is exact in double
    float beta = (float)((double)(2.8125 * (double)v) * 0.017453292519943295);
    float cb, sb;
    __sincosf(beta, &sb, &cb);          // fast approx — replaced below for accuracy
    cb = cosf(beta);
    sb = sinf(beta);

    float u  = ((float)n - 255.5f) * DET_ELT;      // detector offset (DET_OFF = 0)
    float dx = -SDDf * cb - u * sb;                // det - src
    float dy = -SDDf * sb + u * cb;
    float inv = rsqrtf(dx * dx + dy * dy);
    dx *= inv; dy *= inv;                          // unit ray direction

    const float t0  = SIDf - Rf;
    float jx0 = fmaf(t0, dx, SIDf * cb) + 127.5f;  // jx at s=0
    float iy0 = 127.5f - fmaf(t0, dy, SIDf * sb);  // iy at s=0
    float djx = dx;                                // per-sample increments (STEP=1, PIX=1)
    float diy = -dy;

    // ---- clip s to the region where floor(jx),floor(iy) stay in padded range ----
    // any sample with coord outside [-1, 256) contributes exactly 0, so clipping
    // at [-1.5, 256.5] is loss-free; PAD=4 absorbs up to ±2.5 px of slack.
    const float LO = -1.5f, HI = 256.5f;
    float slo = 0.f, shi = (float)(NS - 1);
    {
        float s1 = (LO - jx0) / djx, s2 = (HI - jx0) / djx;
        slo = fmaxf(slo, fminf(s1, s2));
        shi = fminf(shi, fmaxf(s1, s2));
        s1 = (LO - iy0) / diy; s2 = (HI - iy0) / diy;
        slo = fmaxf(slo, fminf(s1, s2));
        shi = fminf(shi, fmaxf(s1, s2));
    }
    int is = (int)fminf(fmaxf(ceilf(slo),  0.f), (float)(NS - 1));
    int ie = (int)fminf(fmaxf(floorf(shi), -1.f), (float)(NS - 1));

    float acc0 = 0.f, acc1 = 0.f;
    const float4* __restrict__ pk = g_pack;

    #pragma unroll 4
    for (int s = is; s <= ie; ++s) {
        float fs  = (float)s;
        float jx  = fmaf(fs, djx, jx0);
        float iy  = fmaf(fs, diy, iy0);
        float j0f = floorf(jx);
        float i0f = floorf(iy);
        float fj  = jx - j0f;
        float fi  = iy - i0f;
        int   j0  = (int)j0f;
        int   i0  = (int)i0f;
        int   base = (i0 + PAD) * PW + (j0 + PAD);
        float4 a = pk[base];          // row i0  : {x0(j0), x1(j0), x0(j0+1), x1(j0+1)}
        float4 b = pk[base + PW];     // row i0+1
        float top0 = fmaf(fj, a.z - a.x, a.x);
        float top1 = fmaf(fj, a.w - a.y, a.y);
        float bot0 = fmaf(fj, b.z - b.x, b.x);
        float bot1 = fmaf(fj, b.w - b.y, b.y);
        acc0 += fmaf(fi, bot0 - top0, top0);
        acc1 += fmaf(fi, bot1 - top1, top1);
    }

    // STEP = 1.0, so the line-integral scale is a no-op
    out[v * NDET + n]                 = acc0;
    out[VIEWS * NDET + v * NDET + n]  = acc1;
}

// ---------------- launch ----------------
extern "C" void kernel_launch(void* const* d_in, const int* in_sizes, int n_in,
                              void* d_out, int out_size) {
    const float* x = (const float*)d_in[0];
    float* out = (float*)d_out;
    (void)in_sizes; (void)n_in; (void)out_size;

    pack_kernel<<<(PH * PW + 255) / 256, 256>>>(x);
    fpj_kernel<<<dim3(NDET / 128, VIEWS), 128>>>(out);
}

// round 2
// speedup vs baseline: 1.4992x; 1.4992x over previous
#include <cuda_runtime.h>
#include <math.h>

// ---------------- problem constants ----------------
#define IMG     256
#define VIEWS   128
#define NDET    512
#define NS      364          // ceil(2R/STEP)+1, R = 256*sqrt(2)/2
#define SIDf    750.0f
#define SDDf    1250.0f
#define DET_ELT 1.2f
#define Rf      181.01933598375618f   // 256*sqrt(2)/2

// ---------------- packed padded image ----------------
// cell (i,j) holds {x0(i,j), x1(i,j), x0(i,j+1), x1(i,j+1)}
// padded by PAD cells of zeros on every side: all clipped-range gathers are
// branch-free; out-of-image corners contribute exactly 0.
#define PAD 4
#define PW  272
#define PH  272

__device__ float4 g_pack[PH * PW];

__global__ void pack_kernel(const float* __restrict__ x) {
    int idx = blockIdx.x * blockDim.x + threadIdx.x;
    if (idx >= PH * PW) return;
    int row = idx / PW, col = idx % PW;
    int i = row - PAD, j = col - PAD;
    float a = 0.f, b = 0.f, c = 0.f, d = 0.f;
    if (i >= 0 && i < IMG) {
        if (j >= 0 && j < IMG) {
            a = x[i * IMG + j];
            b = x[IMG * IMG + i * IMG + j];
        }
        int j1 = j + 1;
        if (j1 >= 0 && j1 < IMG) {
            c = x[i * IMG + j1];
            d = x[IMG * IMG + i * IMG + j1];
        }
    }
    g_pack[idx] = make_float4(a, b, c, d);
}

// ---------------- main projection kernel ----------------
// Block = 32 detectors x CHUNK s-segments. Each thread integrates a quarter of
// the clipped sample range for one (view, detector) ray; shared-memory
// reduction combines the 4 partial sums. Lanes 0..31 = adjacent detectors at
// the same sample index -> warp gathers stay spatially coalesced.
#define CHUNK 4

__global__ void __launch_bounds__(128, 16) fpj_kernel(float* __restrict__ out) {
    const int lane  = threadIdx.x & 31;        // detector within group
    const int chunk = threadIdx.x >> 5;        // 0..3 segment id
    const int n = blockIdx.x * 32 + lane;      // detector index
    const int v = blockIdx.y;                  // view index

    // ---- geometry (matches reference float32 math) ----
    float beta = (float)((double)(2.8125 * (double)v) * 0.017453292519943295);
    float cb = cosf(beta);
    float sb = sinf(beta);

    float u  = ((float)n - 255.5f) * DET_ELT;      // DET_OFF = 0
    float dx = -SDDf * cb - u * sb;                // det - src
    float dy = -SDDf * sb + u * cb;
    float inv = rsqrtf(dx * dx + dy * dy);
    dx *= inv; dy *= inv;                          // unit ray direction

    const float t0  = SIDf - Rf;
    float jx0 = fmaf(t0, dx, SIDf * cb) + 127.5f;  // jx at s=0
    float iy0 = 127.5f - fmaf(t0, dy, SIDf * sb);  // iy at s=0
    float djx = dx;                                // STEP=1, PIX=1
    float diy = -dy;

    // ---- clip s to where both coords stay in [-1.5, 256.5] (loss-free) ----
    const float LO = -1.5f, HI = 256.5f;
    float slo = 0.f, shi = (float)(NS - 1);
    {
        float s1 = (LO - jx0) / djx, s2 = (HI - jx0) / djx;
        slo = fmaxf(slo, fminf(s1, s2));
        shi = fminf(shi, fmaxf(s1, s2));
        s1 = (LO - iy0) / diy; s2 = (HI - iy0) / diy;
        slo = fmaxf(slo, fminf(s1, s2));
        shi = fminf(shi, fmaxf(s1, s2));
    }
    int is = (int)fminf(fmaxf(ceilf(slo),  0.f), (float)(NS - 1));
    int ie = (int)fminf(fmaxf(floorf(shi), -1.f), (float)(NS - 1));

    // ---- this thread's sub-segment ----
    int len = ie - is + 1;
    int per = (len + CHUNK - 1) >> 2;              // ceil(len/4), <=0 if empty
    int cs  = is + chunk * per;
    int ce  = cs + per - 1;
    if (ce > ie) ce = ie;

    float acc0 = 0.f, acc1 = 0.f;
    const float4* __restrict__ pk = g_pack;

    #pragma unroll 4
    for (int s = cs; s <= ce; ++s) {
        float fs  = (float)s;
        float jx  = fmaf(fs, djx, jx0);
        float iy  = fmaf(fs, diy, iy0);
        float j0f = floorf(jx);
        float i0f = floorf(iy);
        float fj  = jx - j0f;
        float fi  = iy - i0f;
        int   j0  = (int)j0f;
        int   i0  = (int)i0f;
        int   base = (i0 + PAD) * PW + (j0 + PAD);
        float4 a = pk[base];          // row i0  : {x0(j0), x1(j0), x0(j0+1), x1(j0+1)}
        float4 b = pk[base + PW];     // row i0+1
        float top0 = fmaf(fj, a.z - a.x, a.x);
        float top1 = fmaf(fj, a.w - a.y, a.y);
        float bot0 = fmaf(fj, b.z - b.x, b.x);
        float bot1 = fmaf(fj, b.w - b.y, b.y);
        acc0 += fmaf(fi, bot0 - top0, top0);
        acc1 += fmaf(fi, bot1 - top1, top1);
    }

    // ---- reduce the 4 segment partials per detector ----
    __shared__ float r0[128];
    __shared__ float r1[128];
    r0[threadIdx.x] = acc0;
    r1[threadIdx.x] = acc1;
    __syncthreads();

    if (chunk == 0) {
        float t0s = r0[lane] + r0[lane + 32] + r0[lane + 64] + r0[lane + 96];
        float t1s = r1[lane] + r1[lane + 32] + r1[lane + 64] + r1[lane + 96];
        out[v * NDET + n]                = t0s;   // STEP = 1.0 scale is a no-op
        out[VIEWS * NDET + v * NDET + n] = t1s;
    }
}

// ---------------- launch ----------------
extern "C" void kernel_launch(void* const* d_in, const int* in_sizes, int n_in,
                              void* d_out, int out_size) {
    const float* x = (const float*)d_in[0];
    float* out = (float*)d_out;
    (void)in_sizes; (void)n_in; (void)out_size;

    pack_kernel<<<(PH * PW + 255) / 256, 256>>>(x);
    fpj_kernel<<<dim3(NDET / 32, VIEWS), 128>>>(out);
}

// round 3
// speedup vs baseline: 1.8139x; 1.2099x over previous
#include <cuda_runtime.h>
#include <math.h>

// ---------------- problem constants ----------------
#define IMG     256
#define VIEWS   128
#define NDET    512
#define NS      364          // ceil(2R/STEP)+1, R = 256*sqrt(2)/2
#define SIDf    750.0f
#define SDDf    1250.0f
#define DET_ELT 1.2f
#define Rf      181.01933598375618f   // 256*sqrt(2)/2

// ---------------- packed padded images (two layouts) ----------------
// normal:     g_pack [i+PAD][j+PAD] = {x0(i,j), x1(i,j), x0(i,j+1), x1(i,j+1)}  (pair along j)
// transposed: g_packT[j+PAD][i+PAD] = {x0(i,j), x1(i,j), x0(i+1,j), x1(i+1,j)}  (pair along i)
// PAD zeros on every side: clipped-range gathers are branch-free, out-of-image
// corners contribute exactly 0.
#define PAD 4
#define PW  272
#define PH  272

__device__ float4 g_pack [PH * PW];
__device__ float4 g_packT[PH * PW];
__device__ float2 g_view[VIEWS];      // (cos beta, sin beta)

__global__ void pack_kernel(const float* __restrict__ x) {
    int idx = blockIdx.x * blockDim.x + threadIdx.x;
    if (idx < VIEWS) {
        float beta = (float)((double)(2.8125 * (double)idx) * 0.017453292519943295);
        g_view[idx] = make_float2(cosf(beta), sinf(beta));
    }
    if (idx >= PH * PW) return;
    int row = idx / PW, col = idx % PW;

    // normal layout: i = row-PAD, j = col-PAD, pair (j, j+1)
    {
        int i = row - PAD, j = col - PAD;
        float a = 0.f, b = 0.f, c = 0.f, d = 0.f;
        if (i >= 0 && i < IMG) {
            if (j >= 0 && j < IMG) {
                a = x[i * IMG + j];
                b = x[IMG * IMG + i * IMG + j];
            }
            int j1 = j + 1;
            if (j1 >= 0 && j1 < IMG) {
                c = x[i * IMG + j1];
                d = x[IMG * IMG + i * IMG + j1];
            }
        }
        g_pack[idx] = make_float4(a, b, c, d);
    }
    // transposed layout: j = row-PAD, i = col-PAD, pair (i, i+1)
    {
        int j = row - PAD, i = col - PAD;
        float a = 0.f, b = 0.f, c = 0.f, d = 0.f;
        if (j >= 0 && j < IMG) {
            if (i >= 0 && i < IMG) {
                a = x[i * IMG + j];
                b = x[IMG * IMG + i * IMG + j];
            }
            int i1 = i + 1;
            if (i1 >= 0 && i1 < IMG) {
                c = x[i1 * IMG + j];
                d = x[IMG * IMG + i1 * IMG + j];
            }
        }
        g_packT[idx] = make_float4(a, b, c, d);
    }
}

// ---------------- main projection kernel ----------------
// Block = 32 detectors x CHUNK s-segments (256 threads). Lanes 0..31 are
// adjacent detectors at the same sample index; the per-view layout choice
// keeps their footprint along the contiguous float4 axis.
#define CHUNK 8

__global__ void __launch_bounds__(256, 8) fpj_kernel(float* __restrict__ out) {
    const int lane  = threadIdx.x & 31;        // detector within group
    const int chunk = threadIdx.x >> 5;        // 0..7 segment id
    const int n = blockIdx.x * 32 + lane;      // detector index
    const int v = blockIdx.y;                  // view index

    // ---- geometry (float32 math matching the reference) ----
    float2 cs2 = g_view[v];
    float cb = cs2.x, sb = cs2.y;

    float u  = ((float)n - 255.5f) * DET_ELT;      // DET_OFF = 0
    float dx = -SDDf * cb - u * sb;                // det - src
    float dy = -SDDf * sb + u * cb;
    float inv = rsqrtf(dx * dx + dy * dy);
    dx *= inv; dy *= inv;                          // unit ray direction

    const float t0  = SIDf - Rf;
    float jx0 = fmaf(t0, dx, SIDf * cb) + 127.5f;  // jx at s=0
    float iy0 = 127.5f - fmaf(t0, dy, SIDf * sb);  // iy at s=0
    float djx = dx;                                // STEP=1, PIX=1
    float diy = -dy;

    // ---- clip s to where both coords stay in [-1.5, 256.5] (loss-free) ----
    const float LO = -1.5f, HI = 256.5f;
    float slo = 0.f, shi = (float)(NS - 1);
    {
        float s1 = (LO - jx0) / djx, s2 = (HI - jx0) / djx;
        slo = fmaxf(slo, fminf(s1, s2));
        shi = fminf(shi, fmaxf(s1, s2));
        s1 = (LO - iy0) / diy; s2 = (HI - iy0) / diy;
        slo = fmaxf(slo, fminf(s1, s2));
        shi = fminf(shi, fmaxf(s1, s2));
    }
    int is = (int)fminf(fmaxf(ceilf(slo),  0.f), (float)(NS - 1));
    int ie = (int)fminf(fmaxf(floorf(shi), -1.f), (float)(NS - 1));

    // ---- choose layout: detector tangent eu = (-sb, cb).
    // |cb| >= |sb| -> footprint varies along i -> transposed array.
    // (uniform per view: no divergence)
    bool trans = fabsf(cb) >= fabsf(sb);
    const float4* __restrict__ pk = trans ? g_packT : g_pack;
    // fast coord = contiguous (paired) axis inside the chosen layout
    float u0 = trans ? iy0 : jx0;
    float du = trans ? diy : djx;
    float w0 = trans ? jx0 : iy0;
    float dw = trans ? djx : diy;

    // ---- this thread's sub-segment ----
    int len = ie - is + 1;
    int per = (len + CHUNK - 1) >> 3;              // ceil(len/8)
    int cs  = is + chunk * per;
    int ce  = cs + per - 1;
    if (ce > ie) ce = ie;

    float acc0 = 0.f, acc1 = 0.f;

    #pragma unroll 4
    for (int s = cs; s <= ce; ++s) {
        float fs  = (float)s;
        float fu  = fmaf(fs, du, u0);
        float fw  = fmaf(fs, dw, w0);
        float u0f = floorf(fu);
        float w0f = floorf(fw);
        float gu  = fu - u0f;          // frac along fast (paired) axis
        float gw  = fw - w0f;          // frac along slow (row) axis
        int   ui  = (int)u0f;
        int   wi  = (int)w0f;
        int   base = (wi + PAD) * PW + (ui + PAD);
        float4 a = pk[base];           // slow=wi  : {b0(u), b1(u), b0(u+1), b1(u+1)}
        float4 b = pk[base + PW];      // slow=wi+1
        float t0v = fmaf(gu, a.z - a.x, a.x);
        float t1v = fmaf(gu, a.w - a.y, a.y);
        float b0v = fmaf(gu, b.z - b.x, b.x);
        float b1v = fmaf(gu, b.w - b.y, b.y);
        acc0 += fmaf(gw, b0v - t0v, t0v);
        acc1 += fmaf(gw, b1v - t1v, t1v);
    }

    // ---- reduce the CHUNK segment partials per detector ----
    __shared__ float r0[256];
    __shared__ float r1[256];
    r0[threadIdx.x] = acc0;
    r1[threadIdx.x] = acc1;
    __syncthreads();

    if (chunk == 0) {
        float s0 = 0.f, s1 = 0.f;
        #pragma unroll
        for (int c = 0; c < CHUNK; ++c) {
            s0 += r0[lane + 32 * c];
            s1 += r1[lane + 32 * c];
        }
        out[v * NDET + n]                = s0;    // STEP = 1.0 scale is a no-op
        out[VIEWS * NDET + v * NDET + n] = s1;
    }
}

// ---------------- launch ----------------
extern "C" void kernel_launch(void* const* d_in, const int* in_sizes, int n_in,
                              void* d_out, int out_size) {
    const float* x = (const float*)d_in[0];
    float* out = (float*)d_out;
    (void)in_sizes; (void)n_in; (void)out_size;

    pack_kernel<<<(PH * PW + 255) / 256, 256>>>(x);
    fpj_kernel<<<dim3(NDET / 32, VIEWS), 256>>>(out);
}

// round 4
// speedup vs baseline: 2.6328x; 1.4515x over previous
#include <cuda_runtime.h>
#include <cuda_fp16.h>
#include <math.h>

// ---------------- problem constants ----------------
#define IMG     256
#define VIEWS   128
#define NDET    512
#define NS      364          // ceil(2R/STEP)+1, R = 256*sqrt(2)/2
#define SIDf    750.0f
#define SDDf    1250.0f
#define DET_ELT 1.2f
#define Rf      181.01933598375618f   // 256*sqrt(2)/2

// ---------------- packed padded images (fp16, full bilinear stencil / cell) ----
// normal layout, cell (i,j) [16B]:
//   { b0(i,j),   b1(i,j),   b0(i,j+1),   b1(i,j+1),
//     b0(i+1,j), b1(i+1,j), b0(i+1,j+1), b1(i+1,j+1) }   (fast axis = j)
// transposed layout swaps the roles of i and j (fast axis = i).
// PAD zero cells on every side -> clipped-range gathers are branch-free and
// out-of-image corners contribute exactly 0.
#define PAD 4
#define PW  272
#define PH  272

__device__ uint4  g_pack [PH * PW];
__device__ uint4  g_packT[PH * PW];
__device__ float2 g_view[VIEWS];      // (cos beta, sin beta)

__device__ __forceinline__ float imgval(const float* x, int b, int i, int j) {
    if (i < 0 || i >= IMG || j < 0 || j >= IMG) return 0.f;
    return x[b * IMG * IMG + i * IMG + j];
}

__global__ void pack_kernel(const float* __restrict__ x) {
    int idx = blockIdx.x * blockDim.x + threadIdx.x;
    if (idx < VIEWS) {
        float beta = (float)((double)(2.8125 * (double)idx) * 0.017453292519943295);
        g_view[idx] = make_float2(cosf(beta), sinf(beta));
    }
    if (idx >= PH * PW) return;
    int row = idx / PW, col = idx % PW;

    // normal: slow = i = row-PAD, fast = j = col-PAD
    {
        int i = row - PAD, j = col - PAD;
        __half h[8];
        h[0] = __float2half_rn(imgval(x, 0, i,     j));
        h[1] = __float2half_rn(imgval(x, 1, i,     j));
        h[2] = __float2half_rn(imgval(x, 0, i,     j + 1));
        h[3] = __float2half_rn(imgval(x, 1, i,     j + 1));
        h[4] = __float2half_rn(imgval(x, 0, i + 1, j));
        h[5] = __float2half_rn(imgval(x, 1, i + 1, j));
        h[6] = __float2half_rn(imgval(x, 0, i + 1, j + 1));
        h[7] = __float2half_rn(imgval(x, 1, i + 1, j + 1));
        g_pack[idx] = *reinterpret_cast<uint4*>(h);
    }
    // transposed: slow = j = row-PAD, fast = i = col-PAD
    {
        int j = row - PAD, i = col - PAD;
        __half h[8];
        h[0] = __float2half_rn(imgval(x, 0, i,     j));
        h[1] = __float2half_rn(imgval(x, 1, i,     j));
        h[2] = __float2half_rn(imgval(x, 0, i + 1, j));
        h[3] = __float2half_rn(imgval(x, 1, i + 1, j));
        h[4] = __float2half_rn(imgval(x, 0, i,     j + 1));
        h[5] = __float2half_rn(imgval(x, 1, i,     j + 1));
        h[6] = __float2half_rn(imgval(x, 0, i + 1, j + 1));
        h[7] = __float2half_rn(imgval(x, 1, i + 1, j + 1));
        g_packT[idx] = *reinterpret_cast<uint4*>(h);
    }
}

// ---------------- main projection kernel ----------------
// Block = 32 detectors x CHUNK s-segments (256 threads). One LDG.128 fetches
// the full bilinear stencil for both batches; interpolation in fp32.
#define CHUNK 8

__global__ void __launch_bounds__(256, 8) fpj_kernel(float* __restrict__ out) {
    const int lane  = threadIdx.x & 31;        // detector within group
    const int chunk = threadIdx.x >> 5;        // 0..7 segment id
    const int n = blockIdx.x * 32 + lane;      // detector index
    const int v = blockIdx.y;                  // view index

    // ---- geometry (float32 math matching the reference) ----
    float2 cs2 = g_view[v];
    float cb = cs2.x, sb = cs2.y;

    float u  = ((float)n - 255.5f) * DET_ELT;      // DET_OFF = 0
    float dx = -SDDf * cb - u * sb;                // det - src
    float dy = -SDDf * sb + u * cb;
    float inv = rsqrtf(dx * dx + dy * dy);
    dx *= inv; dy *= inv;                          // unit ray direction

    const float t0  = SIDf - Rf;
    float jx0 = fmaf(t0, dx, SIDf * cb) + 127.5f;  // jx at s=0
    float iy0 = 127.5f - fmaf(t0, dy, SIDf * sb);  // iy at s=0
    float djx = dx;                                // STEP=1, PIX=1
    float diy = -dy;

    // ---- clip s to where both coords stay in [-1.5, 256.5] (loss-free) ----
    const float LO = -1.5f, HI = 256.5f;
    float slo = 0.f, shi = (float)(NS - 1);
    {
        float s1 = (LO - jx0) / djx, s2 = (HI - jx0) / djx;
        slo = fmaxf(slo, fminf(s1, s2));
        shi = fminf(shi, fmaxf(s1, s2));
        s1 = (LO - iy0) / diy; s2 = (HI - iy0) / diy;
        slo = fmaxf(slo, fminf(s1, s2));
        shi = fminf(shi, fmaxf(s1, s2));
    }
    int is = (int)fminf(fmaxf(ceilf(slo),  0.f), (float)(NS - 1));
    int ie = (int)fminf(fmaxf(floorf(shi), -1.f), (float)(NS - 1));

    // ---- layout choice: detector tangent eu = (-sb, cb); pick the array whose
    // fast axis tracks the warp footprint (uniform per view, no divergence) ----
    bool trans = fabsf(cb) >= fabsf(sb);
    const uint4* __restrict__ pk = trans ? g_packT : g_pack;
    float u0 = trans ? iy0 : jx0;   // fast coord
    float du = trans ? diy : djx;
    float w0 = trans ? jx0 : iy0;   // slow coord
    float dw = trans ? djx : diy;

    // ---- this thread's sub-segment ----
    int len = ie - is + 1;
    int per = (len + CHUNK - 1) >> 3;              // ceil(len/8)
    int cs  = is + chunk * per;
    int ce  = cs + per - 1;
    if (ce > ie) ce = ie;

    float acc0 = 0.f, acc1 = 0.f;

    #pragma unroll 4
    for (int s = cs; s <= ce; ++s) {
        float fs  = (float)s;
        float fu  = fmaf(fs, du, u0);
        float fw  = fmaf(fs, dw, w0);
        float u0f = floorf(fu);
        float w0f = floorf(fw);
        float gu  = fu - u0f;          // frac along fast axis
        float gw  = fw - w0f;          // frac along slow axis
        int   ui  = (int)u0f;
        int   wi  = (int)w0f;
        int   base = (wi + PAD) * PW + (ui + PAD);

        uint4 raw = pk[base];          // full stencil, both batches
        float2 p00 = __half22float2(*reinterpret_cast<const __half2*>(&raw.x)); // (w  ,u  )
        float2 p01 = __half22float2(*reinterpret_cast<const __half2*>(&raw.y)); // (w  ,u+1)
        float2 p10 = __half22float2(*reinterpret_cast<const __half2*>(&raw.z)); // (w+1,u  )
        float2 p11 = __half22float2(*reinterpret_cast<const __half2*>(&raw.w)); // (w+1,u+1)

        float t0v = fmaf(gu, p01.x - p00.x, p00.x);
        float t1v = fmaf(gu, p01.y - p00.y, p00.y);
        float b0v = fmaf(gu, p11.x - p10.x, p10.x);
        float b1v = fmaf(gu, p11.y - p10.y, p10.y);
        acc0 += fmaf(gw, b0v - t0v, t0v);
        acc1 += fmaf(gw, b1v - t1v, t1v);
    }

    // ---- reduce the CHUNK segment partials per detector ----
    __shared__ float r0[256];
    __shared__ float r1[256];
    r0[threadIdx.x] = acc0;
    r1[threadIdx.x] = acc1;
    __syncthreads();

    if (chunk == 0) {
        float s0 = 0.f, s1 = 0.f;
        #pragma unroll
        for (int c = 0; c < CHUNK; ++c) {
            s0 += r0[lane + 32 * c];
            s1 += r1[lane + 32 * c];
        }
        out[v * NDET + n]                = s0;    // STEP = 1.0 scale is a no-op
        out[VIEWS * NDET + v * NDET + n] = s1;
    }
}

// ---------------- launch ----------------
extern "C" void kernel_launch(void* const* d_in, const int* in_sizes, int n_in,
                              void* d_out, int out_size) {
    const float* x = (const float*)d_in[0];
    float* out = (float*)d_out;
    (void)in_sizes; (void)n_in; (void)out_size;

    pack_kernel<<<(PH * PW + 255) / 256, 256>>>(x);
    fpj_kernel<<<dim3(NDET / 32, VIEWS), 256>>>(out);
}

// round 5
// speedup vs baseline: 2.8304x; 1.0750x over previous
#include <cuda_runtime.h>
#include <cuda_fp16.h>
#include <math.h>

// ---------------- problem constants ----------------
#define IMG     256
#define VIEWS   128
#define NDET    512
#define NS      364          // ceil(2R/STEP)+1, R = 256*sqrt(2)/2
#define SIDf    750.0f
#define SDDf    1250.0f
#define DET_ELT 1.2f
#define Rf      181.01933598375618f   // 256*sqrt(2)/2

// ---------------- packed padded images (fp16, full bilinear stencil / cell) ----
// normal layout, cell (i,j) [16B]:
//   { b0(i,j),   b1(i,j),   b0(i,j+1),   b1(i,j+1),
//     b0(i+1,j), b1(i+1,j), b0(i+1,j+1), b1(i+1,j+1) }   (fast axis = j)
// transposed layout swaps i and j (fast axis = i).
// PAD zero cells on every side -> clipped-range gathers are branch-free and
// out-of-image corners contribute exactly 0.
#define PAD 4
#define PW  272
#define PH  272

__device__ uint4  g_pack [PH * PW];
__device__ uint4  g_packT[PH * PW];
__device__ float2 g_view[VIEWS];      // (cos beta, sin beta)

__device__ __forceinline__ float imgval(const float* x, int b, int i, int j) {
    if (i < 0 || i >= IMG || j < 0 || j >= IMG) return 0.f;
    return x[b * IMG * IMG + i * IMG + j];
}

// blockIdx.y = 0 -> normal layout, 1 -> transposed layout
__global__ void pack_kernel(const float* __restrict__ x) {
    int idx = blockIdx.x * blockDim.x + threadIdx.x;
    if (blockIdx.y == 0 && idx < VIEWS) {
        float beta = (float)((double)(2.8125 * (double)idx) * 0.017453292519943295);
        g_view[idx] = make_float2(cosf(beta), sinf(beta));
    }
    if (idx >= PH * PW) return;
    int row = idx / PW, col = idx % PW;

    __half h[8];
    if (blockIdx.y == 0) {
        int i = row - PAD, j = col - PAD;
        h[0] = __float2half_rn(imgval(x, 0, i,     j));
        h[1] = __float2half_rn(imgval(x, 1, i,     j));
        h[2] = __float2half_rn(imgval(x, 0, i,     j + 1));
        h[3] = __float2half_rn(imgval(x, 1, i,     j + 1));
        h[4] = __float2half_rn(imgval(x, 0, i + 1, j));
        h[5] = __float2half_rn(imgval(x, 1, i + 1, j));
        h[6] = __float2half_rn(imgval(x, 0, i + 1, j + 1));
        h[7] = __float2half_rn(imgval(x, 1, i + 1, j + 1));
        g_pack[idx] = *reinterpret_cast<uint4*>(h);
    } else {
        int j = row - PAD, i = col - PAD;
        h[0] = __float2half_rn(imgval(x, 0, i,     j));
        h[1] = __float2half_rn(imgval(x, 1, i,     j));
        h[2] = __float2half_rn(imgval(x, 0, i + 1, j));
        h[3] = __float2half_rn(imgval(x, 1, i + 1, j));
        h[4] = __float2half_rn(imgval(x, 0, i,     j + 1));
        h[5] = __float2half_rn(imgval(x, 1, i,     j + 1));
        h[6] = __float2half_rn(imgval(x, 0, i + 1, j + 1));
        h[7] = __float2half_rn(imgval(x, 1, i + 1, j + 1));
        g_packT[idx] = *reinterpret_cast<uint4*>(h);
    }
}

// ---------------- main projection kernel ----------------
// Block = 32 detectors x CHUNK s-segments (256 threads). One LDG.128 fetches
// the full bilinear stencil for both batches; lerps in half2 SIMD (one
// instruction covers both batch images), accumulation in fp32.
#define CHUNK 8

__global__ void __launch_bounds__(256, 8) fpj_kernel(float* __restrict__ out) {
    const int lane  = threadIdx.x & 31;        // detector within group
    const int chunk = threadIdx.x >> 5;        // 0..7 segment id
    const int n = blockIdx.x * 32 + lane;      // detector index
    const int v = blockIdx.y;                  // view index

    // ---- geometry (float32 math matching the reference) ----
    float2 cs2 = g_view[v];
    float cb = cs2.x, sb = cs2.y;

    float u  = ((float)n - 255.5f) * DET_ELT;      // DET_OFF = 0
    float dx = -SDDf * cb - u * sb;                // det - src
    float dy = -SDDf * sb + u * cb;
    float inv = rsqrtf(dx * dx + dy * dy);
    dx *= inv; dy *= inv;                          // unit ray direction

    const float t0  = SIDf - Rf;
    float jx0 = fmaf(t0, dx, SIDf * cb) + 127.5f;  // jx at s=0
    float iy0 = 127.5f - fmaf(t0, dy, SIDf * sb);  // iy at s=0
    float djx = dx;                                // STEP=1, PIX=1
    float diy = -dy;

    // ---- clip s to where both coords stay in [-1.5, 256.5] (loss-free) ----
    const float LO = -1.5f, HI = 256.5f;
    float slo = 0.f, shi = (float)(NS - 1);
    {
        float s1 = (LO - jx0) / djx, s2 = (HI - jx0) / djx;
        slo = fmaxf(slo, fminf(s1, s2));
        shi = fminf(shi, fmaxf(s1, s2));
        s1 = (LO - iy0) / diy; s2 = (HI - iy0) / diy;
        slo = fmaxf(slo, fminf(s1, s2));
        shi = fminf(shi, fmaxf(s1, s2));
    }
    int is = (int)fminf(fmaxf(ceilf(slo),  0.f), (float)(NS - 1));
    int ie = (int)fminf(fmaxf(floorf(shi), -1.f), (float)(NS - 1));

    // ---- layout choice: detector tangent eu = (-sb, cb); pick the array whose
    // fast axis tracks the warp footprint (uniform per view, no divergence) ----
    bool trans = fabsf(cb) >= fabsf(sb);
    const uint4* __restrict__ pk = trans ? g_packT : g_pack;
    // fold PAD into the origins (lerp continuity makes 1-ulp floor flips benign)
    float u0 = (trans ? iy0 : jx0) + (float)PAD;   // fast coord
    float du =  trans ? diy : djx;
    float w0 = (trans ? jx0 : iy0) + (float)PAD;   // slow coord
    float dw =  trans ? djx : diy;

    // ---- this thread's sub-segment ----
    int len = ie - is + 1;
    int per = (len + CHUNK - 1) >> 3;              // ceil(len/8)
    int cs  = is + chunk * per;
    int ce  = cs + per - 1;
    if (ce > ie) ce = ie;

    float acc0 = 0.f, acc1 = 0.f;

    #pragma unroll 4
    for (int s = cs; s <= ce; ++s) {
        float fs  = (float)s;
        float fu  = fmaf(fs, du, u0);
        float fw  = fmaf(fs, dw, w0);
        float uf  = floorf(fu);
        float wf  = floorf(fw);
        __half2 gu2 = __float2half2_rn(fu - uf);   // frac, fast axis (both batches)
        __half2 gw2 = __float2half2_rn(fw - wf);   // frac, slow axis
        int base = (int)wf * PW + (int)uf;

        uint4 raw = pk[base];                      // full stencil, both batches
        const __half2* h2 = reinterpret_cast<const __half2*>(&raw);
        __half2 p00 = h2[0];                       // (slow  , fast  )
        __half2 p01 = h2[1];                       // (slow  , fast+1)
        __half2 p10 = h2[2];                       // (slow+1, fast  )
        __half2 p11 = h2[3];                       // (slow+1, fast+1)

        __half2 top = __hfma2(gu2, __hsub2(p01, p00), p00);
        __half2 bot = __hfma2(gu2, __hsub2(p11, p10), p10);
        __half2 res = __hfma2(gw2, __hsub2(bot, top), top);
        float2 f = __half22float2(res);
        acc0 += f.x;
        acc1 += f.y;
    }

    // ---- reduce the CHUNK segment partials per detector ----
    __shared__ float r0[256];
    __shared__ float r1[256];
    r0[threadIdx.x] = acc0;
    r1[threadIdx.x] = acc1;
    __syncthreads();

    if (chunk == 0) {
        float s0 = 0.f, s1 = 0.f;
        #pragma unroll
        for (int c = 0; c < CHUNK; ++c) {
            s0 += r0[lane + 32 * c];
            s1 += r1[lane + 32 * c];
        }
        out[v * NDET + n]                = s0;    // STEP = 1.0 scale is a no-op
        out[VIEWS * NDET + v * NDET + n] = s1;
    }
}

// ---------------- launch ----------------
extern "C" void kernel_launch(void* const* d_in, const int* in_sizes, int n_in,
                              void* d_out, int out_size) {
    const float* x = (const float*)d_in[0];
    float* out = (float*)d_out;
    (void)in_sizes; (void)n_in; (void)out_size;

    pack_kernel<<<dim3((PH * PW + 255) / 256, 2), 256>>>(x);
    fpj_kernel<<<dim3(NDET / 32, VIEWS), 256>>>(out);
}

// round 6
// speedup vs baseline: 2.9512x; 1.0427x over previous
#include <cuda_runtime.h>
#include <cuda_fp16.h>
#include <math.h>

// ---------------- problem constants ----------------
#define IMG     256
#define VIEWS   128
#define NDET    512
#define NS      364          // ceil(2R/STEP)+1, R = 256*sqrt(2)/2
#define SIDf    750.0f
#define SDDf    1250.0f
#define DET_ELT 1.2f
#define Rf      181.01933598375618f   // 256*sqrt(2)/2

// ---------------- packed padded images (fp16, full bilinear stencil / cell) ----
// normal layout, cell (i,j) [16B]:
//   { b0(i,j),   b1(i,j),   b0(i,j+1),   b1(i,j+1),
//     b0(i+1,j), b1(i+1,j), b0(i+1,j+1), b1(i+1,j+1) }   (fast axis = j)
// transposed layout swaps i and j (fast axis = i).
// PAD zero cells on every side -> clipped-range gathers are branch-free and
// out-of-image corners contribute exactly 0.
#define PAD 4
#define PW  272
#define PH  272

__device__ uint4  g_pack [PH * PW];
__device__ uint4  g_packT[PH * PW];
__device__ float2 g_view[VIEWS];      // (cos beta, sin beta)

__device__ __forceinline__ float imgval(const float* x, int b, int i, int j) {
    if (i < 0 || i >= IMG || j < 0 || j >= IMG) return 0.f;
    return x[b * IMG * IMG + i * IMG + j];
}

// blockIdx.y = 0 -> normal layout, 1 -> transposed layout
__global__ void pack_kernel(const float* __restrict__ x) {
    int idx = blockIdx.x * blockDim.x + threadIdx.x;
    if (blockIdx.y == 0 && idx < VIEWS) {
        float beta = (float)((double)(2.8125 * (double)idx) * 0.017453292519943295);
        g_view[idx] = make_float2(cosf(beta), sinf(beta));
    }
    if (idx >= PH * PW) return;
    int row = idx / PW, col = idx % PW;

    __half h[8];
    if (blockIdx.y == 0) {
        int i = row - PAD, j = col - PAD;
        h[0] = __float2half_rn(imgval(x, 0, i,     j));
        h[1] = __float2half_rn(imgval(x, 1, i,     j));
        h[2] = __float2half_rn(imgval(x, 0, i,     j + 1));
        h[3] = __float2half_rn(imgval(x, 1, i,     j + 1));
        h[4] = __float2half_rn(imgval(x, 0, i + 1, j));
        h[5] = __float2half_rn(imgval(x, 1, i + 1, j));
        h[6] = __float2half_rn(imgval(x, 0, i + 1, j + 1));
        h[7] = __float2half_rn(imgval(x, 1, i + 1, j + 1));
        g_pack[idx] = *reinterpret_cast<uint4*>(h);
    } else {
        int j = row - PAD, i = col - PAD;
        h[0] = __float2half_rn(imgval(x, 0, i,     j));
        h[1] = __float2half_rn(imgval(x, 1, i,     j));
        h[2] = __float2half_rn(imgval(x, 0, i + 1, j));
        h[3] = __float2half_rn(imgval(x, 1, i + 1, j));
        h[4] = __float2half_rn(imgval(x, 0, i,     j + 1));
        h[5] = __float2half_rn(imgval(x, 1, i,     j + 1));
        h[6] = __float2half_rn(imgval(x, 0, i + 1, j + 1));
        h[7] = __float2half_rn(imgval(x, 1, i + 1, j + 1));
        g_packT[idx] = *reinterpret_cast<uint4*>(h);
    }
}

// ---------------- main projection kernel ----------------
// Block = 32 detectors x CHUNK s-segments (256 threads). One LDG.128 fetches
// the full bilinear stencil for both batches. Inner loop is a 2-sample
// software pipeline: both independent loads issue before either interp uses
// them (MLP=2), hiding the L1tex latency that bound the previous version.
#define CHUNK 8

__device__ __forceinline__ __half2 bilerp2(uint4 raw, __half2 gu2, __half2 gw2) {
    const __half2* h2 = reinterpret_cast<const __half2*>(&raw);
    __half2 top = __hfma2(gu2, __hsub2(h2[1], h2[0]), h2[0]);
    __half2 bot = __hfma2(gu2, __hsub2(h2[3], h2[2]), h2[2]);
    return __hfma2(gw2, __hsub2(bot, top), top);
}

__global__ void __launch_bounds__(256, 6) fpj_kernel(float* __restrict__ out) {
    const int lane  = threadIdx.x & 31;        // detector within group
    const int chunk = threadIdx.x >> 5;        // 0..7 segment id
    const int n = blockIdx.x * 32 + lane;      // detector index
    const int v = blockIdx.y;                  // view index

    // ---- geometry (float32 math matching the reference) ----
    float2 cs2 = g_view[v];
    float cb = cs2.x, sb = cs2.y;

    float u  = ((float)n - 255.5f) * DET_ELT;      // DET_OFF = 0
    float dx = -SDDf * cb - u * sb;                // det - src
    float dy = -SDDf * sb + u * cb;
    float inv = rsqrtf(dx * dx + dy * dy);
    dx *= inv; dy *= inv;                          // unit ray direction

    const float t0  = SIDf - Rf;
    float jx0 = fmaf(t0, dx, SIDf * cb) + 127.5f;  // jx at s=0
    float iy0 = 127.5f - fmaf(t0, dy, SIDf * sb);  // iy at s=0
    float djx = dx;                                // STEP=1, PIX=1
    float diy = -dy;

    // ---- clip s to where both coords stay in [-1.5, 256.5] (loss-free) ----
    const float LO = -1.5f, HI = 256.5f;
    float slo = 0.f, shi = (float)(NS - 1);
    {
        float s1 = (LO - jx0) / djx, s2 = (HI - jx0) / djx;
        slo = fmaxf(slo, fminf(s1, s2));
        shi = fminf(shi, fmaxf(s1, s2));
        s1 = (LO - iy0) / diy; s2 = (HI - iy0) / diy;
        slo = fmaxf(slo, fminf(s1, s2));
        shi = fminf(shi, fmaxf(s1, s2));
    }
    int is = (int)fminf(fmaxf(ceilf(slo),  0.f), (float)(NS - 1));
    int ie = (int)fminf(fmaxf(floorf(shi), -1.f), (float)(NS - 1));

    // ---- layout choice: detector tangent eu = (-sb, cb); pick the array whose
    // fast axis tracks the warp footprint (uniform per view, no divergence) ----
    bool trans = fabsf(cb) >= fabsf(sb);
    const uint4* __restrict__ pk = trans ? g_packT : g_pack;
    // fold PAD into the origins (lerp continuity makes 1-ulp floor flips benign)
    float u0 = (trans ? iy0 : jx0) + (float)PAD;   // fast coord
    float du =  trans ? diy : djx;
    float w0 = (trans ? jx0 : iy0) + (float)PAD;   // slow coord
    float dw =  trans ? djx : diy;

    // ---- this thread's sub-segment ----
    int len = ie - is + 1;
    int per = (len + CHUNK - 1) >> 3;              // ceil(len/8)
    int cs  = is + chunk * per;
    int ce  = cs + per - 1;
    if (ce > ie) ce = ie;

    float acc0 = 0.f, acc1 = 0.f;

    int s = cs;
    #pragma unroll 2
    for (; s + 1 <= ce; s += 2) {
        // ---- addresses for both samples first ----
        float fsA = (float)s;
        float fsB = (float)(s + 1);
        float fuA = fmaf(fsA, du, u0), fwA = fmaf(fsA, dw, w0);
        float fuB = fmaf(fsB, du, u0), fwB = fmaf(fsB, dw, w0);
        float ufA = floorf(fuA), wfA = floorf(fwA);
        float ufB = floorf(fuB), wfB = floorf(fwB);
        int baseA = (int)wfA * PW + (int)ufA;
        int baseB = (int)wfB * PW + (int)ufB;

        // ---- two independent LDG.128s in flight ----
        uint4 rawA = pk[baseA];
        uint4 rawB = pk[baseB];

        __half2 guA = __float2half2_rn(fuA - ufA);
        __half2 gwA = __float2half2_rn(fwA - wfA);
        __half2 guB = __float2half2_rn(fuB - ufB);
        __half2 gwB = __float2half2_rn(fwB - wfB);

        float2 fA = __half22float2(bilerp2(rawA, guA, gwA));
        float2 fB = __half22float2(bilerp2(rawB, guB, gwB));
        acc0 += fA.x + fB.x;
        acc1 += fA.y + fB.y;
    }
    if (s <= ce) {                                 // odd tail
        float fs = (float)s;
        float fu = fmaf(fs, du, u0), fw = fmaf(fs, dw, w0);
        float uf = floorf(fu), wf = floorf(fw);
        uint4 raw = pk[(int)wf * PW + (int)uf];
        float2 f = __half22float2(bilerp2(raw,
                       __float2half2_rn(fu - uf), __float2half2_rn(fw - wf)));
        acc0 += f.x;
        acc1 += f.y;
    }

    // ---- reduce the CHUNK segment partials per detector ----
    __shared__ float r0[256];
    __shared__ float r1[256];
    r0[threadIdx.x] = acc0;
    r1[threadIdx.x] = acc1;
    __syncthreads();

    if (chunk == 0) {
        float s0 = 0.f, s1 = 0.f;
        #pragma unroll
        for (int c = 0; c < CHUNK; ++c) {
            s0 += r0[lane + 32 * c];
            s1 += r1[lane + 32 * c];
        }
        out[v * NDET + n]                = s0;    // STEP = 1.0 scale is a no-op
        out[VIEWS * NDET + v * NDET + n] = s1;
    }
}

// ---------------- launch ----------------
extern "C" void kernel_launch(void* const* d_in, const int* in_sizes, int n_in,
                              void* d_out, int out_size) {
    const float* x = (const float*)d_in[0];
    float* out = (float*)d_out;
    (void)in_sizes; (void)n_in; (void)out_size;

    pack_kernel<<<dim3((PH * PW + 255) / 256, 2), 256>>>(x);
    fpj_kernel<<<dim3(NDET / 32, VIEWS), 256>>>(out);
}